// round 3
// baseline (speedup 1.0000x reference)
#include <cuda_runtime.h>
#include <math.h>

// Fixed shapes per reference.
#define B_SZ     16384
#define G_SZ     256
#define NROWS    (B_SZ * G_SZ)        // 4,194,304 (b,g) rows
#define CLS_ROWS 8192                 // flat cls rows: r < 8192 (both anchors)
#define INV_B    (1.0f / 16384.0f)
#define ROWS_PER_BLOCK 512            // 2 rows per thread, 256 threads
#define NBLOCKS  (NROWS / ROWS_PER_BLOCK)   // 8192

__device__ __forceinline__ float row_loss(const float4 p0, const float4 p1,
                                          const float4 p2, const float4 t0,
                                          const float4 t1, const bool do_cls) {
    float acc = 0.0f;

    // ---------- anchor 0 ----------
    {
        const float gc = t0.x;              // {0,1}; obj_mask == gc
        const float w  = 0.5f + 0.5f * gc;
        const float dc = gc - p0.z;
        acc += w * dc * dc;

        const float doff = t0.z - p0.x;
        acc += 5.0f * gc * doff * doff;

        const float dd = sqrtf(t0.w) - sqrtf(p0.y);
        acc += 5.0f * gc * dd * dd;

        if (do_cls) {
            const float l0 = gc * p0.w;
            const float l1 = gc * p1.x;
            const float l2 = gc * p1.y;
            const int   idx = (int)(gc * t0.y);
            const float m   = fmaxf(l0, fmaxf(l1, l2));
            const float lse = m + logf(expf(l0 - m) + expf(l1 - m) + expf(l2 - m));
            const float li  = (idx == 0) ? l0 : ((idx == 1) ? l1 : l2);
            acc += lse - li;
        }
    }

    // ---------- anchor 1 ----------
    {
        const float gc = t1.x;
        const float w  = 0.5f + 0.5f * gc;
        const float dc = gc - p2.x;
        acc += w * dc * dc;

        const float doff = t1.z - p1.z;
        acc += 5.0f * gc * doff * doff;

        const float dd = sqrtf(t1.w) - sqrtf(p1.w);
        acc += 5.0f * gc * dd * dd;

        if (do_cls) {
            const float l0 = gc * p2.y;
            const float l1 = gc * p2.z;
            const float l2 = gc * p2.w;
            const int   idx = (int)(gc * t1.y);
            const float m   = fmaxf(l0, fmaxf(l1, l2));
            const float lse = m + logf(expf(l0 - m) + expf(l1 - m) + expf(l2 - m));
            const float li  = (idx == 0) ? l0 : ((idx == 1) ? l1 : l2);
            acc += lse - li;
        }
    }
    return acc;
}

__global__ __launch_bounds__(256)
void ensemble_loss_kernel(const float4* __restrict__ pred4,
                          const float4* __restrict__ targ4,
                          float* __restrict__ out) {
    const int base = blockIdx.x * ROWS_PER_BLOCK;
    const int r0   = base + threadIdx.x;         // pass 1 row
    const int r1   = r0 + 256;                   // pass 2 row

    // Front-batch all 10 independent LDG.128s (streaming, evict-first).
    const float4* pa = pred4 + (long long)r0 * 3;
    const float4* pb = pred4 + (long long)r1 * 3;
    const float4* ta = targ4 + (long long)r0 * 2;
    const float4* tb = targ4 + (long long)r1 * 2;

    const float4 p0a = __ldcs(pa + 0);
    const float4 p1a = __ldcs(pa + 1);
    const float4 p2a = __ldcs(pa + 2);
    const float4 p0b = __ldcs(pb + 0);
    const float4 p1b = __ldcs(pb + 1);
    const float4 p2b = __ldcs(pb + 2);
    const float4 t0a = __ldcs(ta + 0);
    const float4 t1a = __ldcs(ta + 1);
    const float4 t0b = __ldcs(tb + 0);
    const float4 t1b = __ldcs(tb + 1);

    const bool do_cls_a = (r0 < CLS_ROWS);       // uniform per block except blocks 0..15
    const bool do_cls_b = (r1 < CLS_ROWS);

    float acc = row_loss(p0a, p1a, p2a, t0a, t1a, do_cls_a)
              + row_loss(p0b, p1b, p2b, t0b, t1b, do_cls_b);

    // ---- intra-warp reduction ----
    #pragma unroll
    for (int off = 16; off > 0; off >>= 1)
        acc += __shfl_down_sync(0xffffffffu, acc, off);

    // ---- intra-block reduction ----
    __shared__ float smem[8];
    const int lane = threadIdx.x & 31;
    const int warp = threadIdx.x >> 5;
    if (lane == 0) smem[warp] = acc;
    __syncthreads();
    if (warp == 0) {
        acc = (lane < 8) ? smem[lane] : 0.0f;
        #pragma unroll
        for (int off = 4; off > 0; off >>= 1)
            acc += __shfl_down_sync(0xffffffffu, acc, off);
        if (lane == 0)
            atomicAdd(out, acc * INV_B);
    }
}

extern "C" void kernel_launch(void* const* d_in, const int* in_sizes, int n_in,
                              void* d_out, int out_size) {
    const float4* pred4 = (const float4*)d_in[0];
    const float4* targ4 = (const float4*)d_in[1];
    float* out = (float*)d_out;

    cudaMemsetAsync(out, 0, sizeof(float));
    ensemble_loss_kernel<<<NBLOCKS, 256>>>(pred4, targ4, out);
}

// round 4
// speedup vs baseline: 1.0278x; 1.0278x over previous
#include <cuda_runtime.h>
#include <math.h>

// Fixed shapes per reference.
#define B_SZ     16384
#define G_SZ     256
#define NROWS    (B_SZ * G_SZ)        // 4,194,304 (b,g) rows
#define CLS_ROWS 8192                 // flat cls rows: r < 8192 (both anchors)
#define INV_B    (1.0f / 16384.0f)
#define NBLOCKS  8192
#define NTHREADS 256

// Single-launch reduction state (self-resetting; valid across graph replays).
__device__ float    g_acc = 0.0f;
__device__ unsigned g_cnt = 0u;

__global__ __launch_bounds__(NTHREADS)
void ensemble_loss_kernel(const float4* __restrict__ pred4,
                          const float4* __restrict__ targ4,
                          float* __restrict__ out) {
    const int tid    = blockIdx.x * NTHREADS + threadIdx.x;
    const int stride = NBLOCKS * NTHREADS;     // 2,097,152 -> exactly 2 iters

    float acc = 0.0f;

    #pragma unroll 2
    for (int r = tid; r < NROWS; r += stride) {
        // pred row: 12 floats = 3x float4; target row: 8 floats = 2x float4
        const float4 p0 = __ldcs(pred4 + (long long)r * 3 + 0); // off0,dur0,conf0,cls0_0
        const float4 p1 = __ldcs(pred4 + (long long)r * 3 + 1); // cls0_1,cls0_2,off1,dur1
        const float4 p2 = __ldcs(pred4 + (long long)r * 3 + 2); // conf1,cls1_0,cls1_1,cls1_2
        const float4 t0 = __ldcs(targ4 + (long long)r * 2 + 0); // conf0,cls0,off0,dur0
        const float4 t1 = __ldcs(targ4 + (long long)r * 2 + 1); // conf1,cls1,off1,dur1

        // ---------- anchor 0 ----------
        {
            const float gc = t0.x;              // {0,1}; obj_mask == gc
            const float w  = 0.5f + 0.5f * gc;
            const float dc = gc - p0.z;
            acc += w * dc * dc;

            const float doff = t0.z - p0.x;
            acc += 5.0f * gc * doff * doff;

            const float dd = sqrtf(t0.w) - sqrtf(p0.y);
            acc += 5.0f * gc * dd * dd;

            if (r < CLS_ROWS) {
                const float l0 = gc * p0.w;
                const float l1 = gc * p1.x;
                const float l2 = gc * p1.y;
                const int   idx = (int)(gc * t0.y);
                const float m   = fmaxf(l0, fmaxf(l1, l2));
                const float lse = m + logf(expf(l0 - m) + expf(l1 - m) + expf(l2 - m));
                const float li  = (idx == 0) ? l0 : ((idx == 1) ? l1 : l2);
                acc += lse - li;
            }
        }

        // ---------- anchor 1 ----------
        {
            const float gc = t1.x;
            const float w  = 0.5f + 0.5f * gc;
            const float dc = gc - p2.x;
            acc += w * dc * dc;

            const float doff = t1.z - p1.z;
            acc += 5.0f * gc * doff * doff;

            const float dd = sqrtf(t1.w) - sqrtf(p1.w);
            acc += 5.0f * gc * dd * dd;

            if (r < CLS_ROWS) {
                const float l0 = gc * p2.y;
                const float l1 = gc * p2.z;
                const float l2 = gc * p2.w;
                const int   idx = (int)(gc * t1.y);
                const float m   = fmaxf(l0, fmaxf(l1, l2));
                const float lse = m + logf(expf(l0 - m) + expf(l1 - m) + expf(l2 - m));
                const float li  = (idx == 0) ? l0 : ((idx == 1) ? l1 : l2);
                acc += lse - li;
            }
        }
    }

    // ---- intra-warp reduction ----
    #pragma unroll
    for (int off = 16; off > 0; off >>= 1)
        acc += __shfl_down_sync(0xffffffffu, acc, off);

    // ---- intra-block reduction ----
    __shared__ float smem[8];
    const int lane = threadIdx.x & 31;
    const int warp = threadIdx.x >> 5;
    if (lane == 0) smem[warp] = acc;
    __syncthreads();
    if (warp == 0) {
        acc = (lane < 8) ? smem[lane] : 0.0f;
        #pragma unroll
        for (int off = 4; off > 0; off >>= 1)
            acc += __shfl_down_sync(0xffffffffu, acc, off);

        if (lane == 0) {
            atomicAdd(&g_acc, acc);
            __threadfence();
            const unsigned done = atomicAdd(&g_cnt, 1u);
            if (done == NBLOCKS - 1u) {
                // Last block: all adds visible. Publish and self-reset.
                out[0] = g_acc * INV_B;
                g_acc  = 0.0f;
                g_cnt  = 0u;
            }
        }
    }
}

extern "C" void kernel_launch(void* const* d_in, const int* in_sizes, int n_in,
                              void* d_out, int out_size) {
    const float4* pred4 = (const float4*)d_in[0];
    const float4* targ4 = (const float4*)d_in[1];
    float* out = (float*)d_out;

    ensemble_loss_kernel<<<NBLOCKS, NTHREADS>>>(pred4, targ4, out);
}